// round 13
// baseline (speedup 1.0000x reference)
#include <cuda_runtime.h>

#define BB  32
#define NN  16384
#define DD  64
#define NSL 7
#define HH  128

// ---- scratch (device globals; no allocations allowed) ----
__device__ float g_k[(size_t)BB*NN*DD];   // stored TRANSPOSED: [b][d][n]
__device__ float g_v[(size_t)BB*NN*DD];   // row-major: [b][n][d]
__device__ float g_slots[BB*NSL*DD];
__device__ float g_q[BB*NSL*DD];
__device__ float g_U[BB*NSL*DD];
__device__ float g_S[BB*NSL];

__device__ __forceinline__ float wred(float v) {
    v += __shfl_xor_sync(0xffffffffu, v, 16);
    v += __shfl_xor_sync(0xffffffffu, v, 8);
    v += __shfl_xor_sync(0xffffffffu, v, 4);
    v += __shfl_xor_sync(0xffffffffu, v, 2);
    v += __shfl_xor_sync(0xffffffffu, v, 1);
    return v;
}

// dummy: 5 of these run first so ncu -s 5 captures proj_kernel
__global__ void dummy_kernel() {}

// ============================================================
// Projection v5: split-j f32x2 packing (dup-free).
// Block: 512 thr, 128 rows x 128 cols (c<64 -> k, else v).
// Thread: 8 rows x 4 cols; acc b64 lanes = (even-j, odd-j) partials.
// Lane rotation jj=(jp+rg)&31 -> conflict-free x LDS.64, 2-way w.
// smem: xs[128][64] + WT[128][64] + params = ~65 KB.
// ============================================================
__global__ void __launch_bounds__(512, 1) proj_kernel(
    const float* __restrict__ inp,
    const float* __restrict__ Wk, const float* __restrict__ bk,
    const float* __restrict__ Wv, const float* __restrict__ bv,
    const float* __restrict__ gin, const float* __restrict__ bin)
{
    extern __shared__ float sm[];
    float* xs      = sm;            // [128 rows][64 j]
    float* WT      = sm + 8192;     // [128 cols][64 j]
    float* bias_sh = sm + 16384;    // [128]
    float* gi      = sm + 16512;    // [64]
    float* bi      = sm + 16576;    // [64]

    int t = threadIdx.x;

    // stage WT[c][j]: coalesced (e = c*64+j)
    for (int e = t; e < 8192; e += 512)
        WT[e] = (e < 4096) ? Wk[e] : Wv[e - 4096];
    if (t < 64) { gi[t] = gin[t]; bi[t] = bin[t]; bias_sh[t] = bk[t]; bias_sh[64+t] = bv[t]; }

    size_t row0 = (size_t)blockIdx.x * 128;
    int b  = (int)(row0 >> 14);
    int n0 = (int)(row0 & 16383);

    // ---- LN: warp per row, 16 warps, 8 passes; plain [r][j] layout ----
    {
        int wr = t >> 5, lj = t & 31;
        for (int pass = 0; pass < 8; pass++) {
            int r = pass*16 + wr;
            const float* xrow = inp + (row0 + r)*DD;
            float a = xrow[lj], c2 = xrow[lj + 32];
            float s = wred(a + c2);
            float ss = wred(a*a + c2*c2);
            float mean = s * (1.f/64.f);
            float var  = ss * (1.f/64.f) - mean*mean;
            float rstd = rsqrtf(var + 1e-5f);
            xs[r*64 + lj]      = (a  - mean)*rstd*gi[lj]      + bi[lj];
            xs[r*64 + lj + 32] = (c2 - mean)*rstd*gi[lj + 32] + bi[lj + 32];
        }
    }
    __syncthreads();

    int rg = t & 15, cg = t >> 4;       // 16 row-groups x 32 col-groups
    int r0 = rg * 8, c0 = cg * 4;

    unsigned long long acc[8][4];
    #pragma unroll
    for (int r = 0; r < 8; r++)
        #pragma unroll
        for (int c = 0; c < 4; c++) acc[r][c] = 0ULL;

    const float* xbase = xs + r0*64;
    const float* wbase = WT + c0*64;

    // ---- mainloop: 32 j-pairs, zero movs, all operands packed ----
    for (int jp = 0; jp < 32; jp++) {
        int jj = ((jp + rg) & 31) * 2;
        unsigned long long w2[4], x2[8];
        #pragma unroll
        for (int c = 0; c < 4; c++)
            w2[c] = *(const unsigned long long*)(wbase + c*64 + jj);
        #pragma unroll
        for (int r = 0; r < 8; r++)
            x2[r] = *(const unsigned long long*)(xbase + r*64 + jj);
        #pragma unroll
        for (int r = 0; r < 8; r++) {
            asm("fma.rn.f32x2 %0, %1, %2, %0;" : "+l"(acc[r][0]) : "l"(x2[r]), "l"(w2[0]));
            asm("fma.rn.f32x2 %0, %1, %2, %0;" : "+l"(acc[r][1]) : "l"(x2[r]), "l"(w2[1]));
            asm("fma.rn.f32x2 %0, %1, %2, %0;" : "+l"(acc[r][2]) : "l"(x2[r]), "l"(w2[2]));
            asm("fma.rn.f32x2 %0, %1, %2, %0;" : "+l"(acc[r][3]) : "l"(x2[r]), "l"(w2[3]));
        }
    }

    // ---- combine even/odd partials + bias ----
    float af[8][4];
    #pragma unroll
    for (int r = 0; r < 8; r++)
        #pragma unroll
        for (int c = 0; c < 4; c++) {
            float lo, hi;
            asm("mov.b64 {%0, %1}, %2;" : "=f"(lo), "=f"(hi) : "l"(acc[r][c]));
            af[r][c] = lo + hi + bias_sh[c0 + c];
        }

    if (c0 < 64) {
        // k transposed: [b][col][n], 8 consecutive n per (thread, col)
        #pragma unroll
        for (int c = 0; c < 4; c++) {
            float* dst = g_k + ((size_t)(b*64 + c0 + c))*NN + n0 + r0;
            ((float4*)dst)[0] = make_float4(af[0][c], af[1][c], af[2][c], af[3][c]);
            ((float4*)dst)[1] = make_float4(af[4][c], af[5][c], af[6][c], af[7][c]);
        }
    } else {
        // v row-major: one float4 per row
        #pragma unroll
        for (int r = 0; r < 8; r++) {
            float* dst = g_v + (row0 + r0 + r)*DD + (c0 - 64);
            *(float4*)dst = make_float4(af[r][0], af[r][1], af[r][2], af[r][3]);
        }
    }
}

// ============================================================
// Attention v2 (unchanged from R12): grid (32, B), 256 thr.
// ============================================================
__global__ void __launch_bounds__(256) attn_kernel()
{
    int b = blockIdx.y;
    int t = threadIdx.x;
    __shared__ __align__(16) float q_sh[NSL*DD];
    __shared__ __align__(16) float attn_sh[512][8];     // 16 KB
    __shared__ __align__(16) float4 red4[16][16][NSL];  // 28 KB
    __shared__ float S_sh[NSL];

    for (int e = t; e < NSL*DD; e += 256) q_sh[e] = g_q[b*NSL*DD + e];
    if (t < NSL) S_sh[t] = 0.f;
    __syncthreads();

    int n0 = blockIdx.x * 512;

    float S_loc[NSL];
    #pragma unroll
    for (int i = 0; i < NSL; i++) S_loc[i] = 0.f;
    {
        const float* kb = g_k + ((size_t)b*64)*NN + n0 + 2*t;
        float acc[NSL][2];
        #pragma unroll
        for (int i = 0; i < NSL; i++) { acc[i][0] = 0.f; acc[i][1] = 0.f; }

        #pragma unroll 4
        for (int dc = 0; dc < 16; dc++) {
            float2 k0 = *(const float2*)(kb + (size_t)(4*dc+0)*NN);
            float2 k1 = *(const float2*)(kb + (size_t)(4*dc+1)*NN);
            float2 k2 = *(const float2*)(kb + (size_t)(4*dc+2)*NN);
            float2 k3 = *(const float2*)(kb + (size_t)(4*dc+3)*NN);
            #pragma unroll
            for (int i = 0; i < NSL; i++) {
                float4 q4 = *(const float4*)&q_sh[i*64 + 4*dc];
                acc[i][0] = fmaf(q4.x, k0.x, acc[i][0]);
                acc[i][1] = fmaf(q4.x, k0.y, acc[i][1]);
                acc[i][0] = fmaf(q4.y, k1.x, acc[i][0]);
                acc[i][1] = fmaf(q4.y, k1.y, acc[i][1]);
                acc[i][0] = fmaf(q4.z, k2.x, acc[i][0]);
                acc[i][1] = fmaf(q4.z, k2.y, acc[i][1]);
                acc[i][0] = fmaf(q4.w, k3.x, acc[i][0]);
                acc[i][1] = fmaf(q4.w, k3.y, acc[i][1]);
            }
        }
        #pragma unroll
        for (int kk = 0; kk < 2; kk++) {
            float mx = acc[0][kk];
            #pragma unroll
            for (int i = 1; i < NSL; i++) mx = fmaxf(mx, acc[i][kk]);
            float e[8]; float ssum = 0.f;
            #pragma unroll
            for (int i = 0; i < NSL; i++) { e[i] = __expf(acc[i][kk] - mx); ssum += e[i]; }
            float inv = __fdividef(1.f, ssum);
            #pragma unroll
            for (int i = 0; i < NSL; i++) {
                float p = fmaf(e[i], inv, 1e-8f);
                e[i] = p; S_loc[i] += p;
            }
            e[7] = 0.f;
            int jl = 2*t + kk;
            *(float4*)&attn_sh[jl][0] = make_float4(e[0], e[1], e[2], e[3]);
            *(float4*)&attn_sh[jl][4] = make_float4(e[4], e[5], e[6], e[7]);
        }
    }
    __syncthreads();

    int g = t >> 4, dq = t & 15;
    float4 U[NSL];
    #pragma unroll
    for (int i = 0; i < NSL; i++) U[i] = make_float4(0.f, 0.f, 0.f, 0.f);
    {
        const float4* vp = (const float4*)(g_v + ((size_t)b*NN + n0 + g*32)*DD) + dq;
        #pragma unroll 4
        for (int jj = 0; jj < 32; jj++) {
            float4 v4 = vp[(size_t)jj*16];
            int jl = g*32 + jj;
            float4 a0 = *(const float4*)&attn_sh[jl][0];
            float4 a1 = *(const float4*)&attn_sh[jl][4];
            U[0].x = fmaf(a0.x, v4.x, U[0].x); U[0].y = fmaf(a0.x, v4.y, U[0].y);
            U[0].z = fmaf(a0.x, v4.z, U[0].z); U[0].w = fmaf(a0.x, v4.w, U[0].w);
            U[1].x = fmaf(a0.y, v4.x, U[1].x); U[1].y = fmaf(a0.y, v4.y, U[1].y);
            U[1].z = fmaf(a0.y, v4.z, U[1].z); U[1].w = fmaf(a0.y, v4.w, U[1].w);
            U[2].x = fmaf(a0.z, v4.x, U[2].x); U[2].y = fmaf(a0.z, v4.y, U[2].y);
            U[2].z = fmaf(a0.z, v4.z, U[2].z); U[2].w = fmaf(a0.z, v4.w, U[2].w);
            U[3].x = fmaf(a0.w, v4.x, U[3].x); U[3].y = fmaf(a0.w, v4.y, U[3].y);
            U[3].z = fmaf(a0.w, v4.z, U[3].z); U[3].w = fmaf(a0.w, v4.w, U[3].w);
            U[4].x = fmaf(a1.x, v4.x, U[4].x); U[4].y = fmaf(a1.x, v4.y, U[4].y);
            U[4].z = fmaf(a1.x, v4.z, U[4].z); U[4].w = fmaf(a1.x, v4.w, U[4].w);
            U[5].x = fmaf(a1.y, v4.x, U[5].x); U[5].y = fmaf(a1.y, v4.y, U[5].y);
            U[5].z = fmaf(a1.y, v4.z, U[5].z); U[5].w = fmaf(a1.y, v4.w, U[5].w);
            U[6].x = fmaf(a1.z, v4.x, U[6].x); U[6].y = fmaf(a1.z, v4.y, U[6].y);
            U[6].z = fmaf(a1.z, v4.z, U[6].z); U[6].w = fmaf(a1.z, v4.w, U[6].w);
        }
    }
    #pragma unroll
    for (int i = 0; i < NSL; i++) red4[g][dq][i] = U[i];
    __syncthreads();

    for (int e = t; e < NSL*DD; e += 256) {
        int i = e >> 6, d = e & 63;
        int dq2 = d >> 2, c = d & 3;
        const float* base = (const float*)&red4[0][dq2][i] + c;
        float s = 0.f;
        #pragma unroll
        for (int gg = 0; gg < 16; gg++)
            s += base[gg*16*NSL*4];
        atomicAdd(&g_U[(b*NSL + i)*DD + d], s);
    }

    #pragma unroll
    for (int i = 0; i < NSL; i++) {
        float sv = wred(S_loc[i]);
        if ((t & 31) == 0) atomicAdd(&S_sh[i], sv);
    }
    __syncthreads();
    if (t < NSL) atomicAdd(&g_S[b*NSL + t], S_sh[t]);
}

// ============================================================
// Prep (unchanged)
// ============================================================
__global__ void __launch_bounds__(448) prep_kernel(
    const float* __restrict__ noise, const float* __restrict__ mu,
    const float* __restrict__ sigma,
    const float* __restrict__ Wq, const float* __restrict__ bq,
    const float* __restrict__ gsl, const float* __restrict__ bsl)
{
    int b = blockIdx.x, t = threadIdx.x;
    __shared__ float sl[NSL*DD], sn[NSL*DD];
    __shared__ float mstat[NSL][2];
    if (t < NSL*DD) {
        int d = t & 63;
        float v = mu[d] + sigma[d]*noise[b*NSL*DD + t];
        sl[t] = v;
        g_slots[b*NSL*DD + t] = v;
        g_U[b*NSL*DD + t] = 0.f;
    }
    if (t < NSL) g_S[b*NSL + t] = 0.f;
    __syncthreads();
    if (t < NSL) {
        float s = 0.f, ss = 0.f;
        for (int j = 0; j < DD; j++) { float x = sl[t*DD + j]; s += x; ss += x*x; }
        float mean = s*(1.f/64.f), var = ss*(1.f/64.f) - mean*mean;
        mstat[t][0] = mean; mstat[t][1] = rsqrtf(var + 1e-5f);
    }
    __syncthreads();
    if (t < NSL*DD) {
        int i = t >> 6, d = t & 63;
        sn[t] = (sl[t] - mstat[i][0])*mstat[i][1]*gsl[d] + bsl[d];
    }
    __syncthreads();
    if (t < NSL*DD) {
        int i = t >> 6, d = t & 63;
        float q = bq[d];
        for (int j = 0; j < DD; j++) q = fmaf(sn[i*DD + j], Wq[d*DD + j], q);
        g_q[b*NSL*DD + t] = q * 0.125f;
    }
}

// ============================================================
// Finish v3 (unchanged)
// ============================================================
__global__ void __launch_bounds__(512) finish_kernel(
    const float* __restrict__ W_ih, const float* __restrict__ W_hh,
    const float* __restrict__ b_ih, const float* __restrict__ b_hh,
    const float* __restrict__ mW1, const float* __restrict__ mb1,
    const float* __restrict__ mW2, const float* __restrict__ mb2,
    const float* __restrict__ gml, const float* __restrict__ bml,
    const float* __restrict__ Wq,  const float* __restrict__ bq,
    const float* __restrict__ gsl, const float* __restrict__ bsl,
    float* __restrict__ out, int is_last)
{
    int slot = blockIdx.x, b = blockIdx.y;
    int t = threadIdx.x, w = t >> 5, lane = t & 31;
    int sb = b*NSL + slot;

    __shared__ float u[64], p[64];
    __shared__ float xg[192], hg[192];
    __shared__ float snew[64], mn[64], hid[128], sfin[64], sq[64];
    __shared__ float stat[2];

    if (t < 64) {
        float S = g_S[sb];
        u[t] = g_U[sb*DD + t] / S;
        p[t] = g_slots[sb*DD + t];
    }
    __syncthreads();
    if (t < 64) g_U[sb*DD + t] = 0.f;
    if (t == 0) g_S[sb] = 0.f;

    float u_lo = u[lane], u_hi = u[lane+32];
    float p_lo = p[lane], p_hi = p[lane+32];
    #pragma unroll
    for (int it = 0; it < 12; it++) {
        int gd = w + 16*it;
        const float* wi = W_ih + gd*DD;
        const float* wh = W_hh + gd*DD;
        float xa = u_lo*wi[lane] + u_hi*wi[lane+32];
        float ha = p_lo*wh[lane] + p_hi*wh[lane+32];
        xa = wred(xa); ha = wred(ha);
        if (lane == 0) { xg[gd] = xa + b_ih[gd]; hg[gd] = ha + b_hh[gd]; }
    }
    __syncthreads();

    if (t < 64) {
        float r = 1.f/(1.f + expf(-(xg[t]      + hg[t])));
        float z = 1.f/(1.f + expf(-(xg[64+t]   + hg[64+t])));
        float n = tanhf(xg[128+t] + r*hg[128+t]);
        snew[t] = (1.f - z)*n + z*p[t];
    }
    __syncthreads();

    if (w == 0) {
        float a = snew[lane], c = snew[lane+32];
        float s  = wred(a + c);
        float ss = wred(a*a + c*c);
        if (lane == 0) {
            float mean = s*(1.f/64.f), var = ss*(1.f/64.f) - mean*mean;
            stat[0] = mean; stat[1] = rsqrtf(var + 1e-5f);
        }
    }
    __syncthreads();
    if (t < 64) mn[t] = (snew[t] - stat[0])*stat[1]*gml[t] + bml[t];
    __syncthreads();

    float m_lo = mn[lane], m_hi = mn[lane+32];
    #pragma unroll
    for (int it = 0; it < 8; it++) {
        int hh = w + 16*it;
        const float* w1 = mW1 + hh*DD;
        float a = m_lo*w1[lane] + m_hi*w1[lane+32];
        a = wred(a);
        if (lane == 0) hid[hh] = fmaxf(a + mb1[hh], 0.f);
    }
    __syncthreads();

    float h0 = hid[lane], h1 = hid[lane+32], h2 = hid[lane+64], h3 = hid[lane+96];
    #pragma unroll
    for (int it = 0; it < 4; it++) {
        int d = w + 16*it;
        const float* w2 = mW2 + d*HH;
        float a = h0*w2[lane] + h1*w2[lane+32] + h2*w2[lane+64] + h3*w2[lane+96];
        a = wred(a);
        if (lane == 0) {
            float vfin = snew[d] + a + mb2[d];
            sfin[d] = vfin;
            g_slots[sb*DD + d] = vfin;
            if (is_last) out[sb*DD + d] = vfin;
        }
    }
    __syncthreads();

    if (w == 0) {
        float a = sfin[lane], c = sfin[lane+32];
        float s  = wred(a + c);
        float ss = wred(a*a + c*c);
        if (lane == 0) {
            float mean = s*(1.f/64.f), var = ss*(1.f/64.f) - mean*mean;
            stat[0] = mean; stat[1] = rsqrtf(var + 1e-5f);
        }
    }
    __syncthreads();
    if (t < 64) sq[t] = (sfin[t] - stat[0])*stat[1]*gsl[t] + bsl[t];
    __syncthreads();

    float s_lo = sq[lane], s_hi = sq[lane+32];
    #pragma unroll
    for (int it = 0; it < 4; it++) {
        int d = w + 16*it;
        const float* wq = Wq + d*DD;
        float a = s_lo*wq[lane] + s_hi*wq[lane+32];
        a = wred(a);
        if (lane == 0) g_q[sb*DD + d] = (a + bq[d]) * 0.125f;
    }
}

// ============================================================
extern "C" void kernel_launch(void* const* d_in, const int* in_sizes, int n_in,
                              void* d_out, int out_size)
{
    const float* inputs = (const float*)d_in[0];
    const float* noise  = (const float*)d_in[1];
    const float* mu     = (const float*)d_in[2];
    const float* sigma  = (const float*)d_in[3];
    const float* Wq     = (const float*)d_in[4];
    const float* bq     = (const float*)d_in[5];
    const float* Wk     = (const float*)d_in[6];
    const float* bk     = (const float*)d_in[7];
    const float* Wv     = (const float*)d_in[8];
    const float* bv     = (const float*)d_in[9];
    const float* W_ih   = (const float*)d_in[10];
    const float* W_hh   = (const float*)d_in[11];
    const float* b_ih   = (const float*)d_in[12];
    const float* b_hh   = (const float*)d_in[13];
    const float* mW1    = (const float*)d_in[14];
    const float* mb1    = (const float*)d_in[15];
    const float* mW2    = (const float*)d_in[16];
    const float* mb2    = (const float*)d_in[17];
    const float* gin    = (const float*)d_in[18];
    const float* bin    = (const float*)d_in[19];
    const float* gsl    = (const float*)d_in[20];
    const float* bsl    = (const float*)d_in[21];
    const float* gml    = (const float*)d_in[22];
    const float* bml    = (const float*)d_in[23];
    float* out = (float*)d_out;

    const int PROJ_SMEM = 16640 * 4;   // xs 8192 + WT 8192 + bias 128 + gi/bi 128 floats
    static int attr_set = 0;
    if (!attr_set) {
        cudaFuncSetAttribute(proj_kernel, cudaFuncAttributeMaxDynamicSharedMemorySize, PROJ_SMEM);
        attr_set = 1;
    }

    // launches 0-4: dummies -> ncu -s 5 captures proj_kernel
    for (int i = 0; i < 5; i++) dummy_kernel<<<1, 32>>>();
    proj_kernel<<<4096, 512, PROJ_SMEM>>>(inputs, Wk, bk, Wv, bv, gin, bin);   // launch 5
    prep_kernel<<<BB, 448>>>(noise, mu, sigma, Wq, bq, gsl, bsl);
    for (int it = 0; it < 3; it++) {
        attn_kernel<<<dim3(32, BB), 256>>>();
        finish_kernel<<<dim3(NSL, BB), 512>>>(W_ih, W_hh, b_ih, b_hh, mW1, mb1, mW2, mb2,
                                              gml, bml, Wq, bq, gsl, bsl, out, (it == 2) ? 1 : 0);
    }
}

// round 14
// speedup vs baseline: 1.6116x; 1.6116x over previous
#include <cuda_runtime.h>

#define BB  32
#define NN  16384
#define DD  64
#define NSL 7
#define HH  128

// ---- scratch (device globals; no allocations allowed) ----
__device__ float g_k[(size_t)BB*NN*DD];   // stored TRANSPOSED: [b][d][n]
__device__ float g_v[(size_t)BB*NN*DD];   // row-major: [b][n][d]
__device__ float g_slots[BB*NSL*DD];
__device__ float g_q[BB*NSL*DD];
__device__ float g_U[BB*NSL*DD];
__device__ float g_S[BB*NSL];

__device__ __forceinline__ float wred(float v) {
    v += __shfl_xor_sync(0xffffffffu, v, 16);
    v += __shfl_xor_sync(0xffffffffu, v, 8);
    v += __shfl_xor_sync(0xffffffffu, v, 4);
    v += __shfl_xor_sync(0xffffffffu, v, 2);
    v += __shfl_xor_sync(0xffffffffu, v, 1);
    return v;
}

__global__ void dummy_kernel() {}

// ============================================================
// Projection v6: v3 GEMM (R12) + smem-staged COALESCED stores.
// Block: 256 thr, 128 rows x 128 cols; thread tile 8x8; f32x2.
// After GEMM, xs/WT regions are dead -> reuse as staging:
//   v staged as [r][(c+4*(r>>3))&63]   (8192 floats, xs region)
//   k staged as [c][n] stride 132      (8448 floats, WT region)
// then warp-contiguous STG.128 (nL=4) for both tensors.
// ============================================================
__global__ void __launch_bounds__(256, 2) proj_kernel(
    const float* __restrict__ inp,
    const float* __restrict__ Wk, const float* __restrict__ bk,
    const float* __restrict__ Wv, const float* __restrict__ bv,
    const float* __restrict__ gin, const float* __restrict__ bin)
{
    extern __shared__ float sm[];
    float* xs      = sm;            // [128][64] swizzled x; later: v staging
    float* WT      = sm + 8192;     // [64][132] weights;     later: k staging
    float* bias_sh = sm + 16640;    // [128]
    float* gi      = sm + 16768;    // [64]
    float* bi      = sm + 16832;    // [64]

    int t = threadIdx.x;

    for (int e = t; e < 8192; e += 256) {
        int c = e >> 6, j = e & 63;
        float w = (c < 64) ? Wk[c*64 + j] : Wv[(c-64)*64 + j];
        WT[j*132 + c] = w;
    }
    if (t < 64) { gi[t] = gin[t]; bi[t] = bin[t]; bias_sh[t] = bk[t]; bias_sh[64+t] = bv[t]; }

    size_t row0 = (size_t)blockIdx.x * 128;
    int b  = (int)(row0 >> 14);
    int n0 = (int)(row0 & 16383);

    // ---- LN (identical to R12) ----
    {
        int lrow = t >> 5;
        int lj   = t & 31;
        for (int pass = 0; pass < 16; pass++) {
            int r = pass*8 + lrow;
            const float* xrow = inp + (row0 + r)*DD;
            float a = xrow[lj], c2 = xrow[lj + 32];
            float s = a + c2, ss = a*a + c2*c2;
            s = wred(s); ss = wred(ss);
            float mean = s * (1.f/64.f);
            float var  = ss * (1.f/64.f) - mean*mean;
            float rstd = rsqrtf(var + 1e-5f);
            int sw = r >> 3;
            xs[r*64 + ((lj      + sw) & 63)] = (a  - mean)*rstd*gi[lj]      + bi[lj];
            xs[r*64 + ((lj + 32 + sw) & 63)] = (c2 - mean)*rstd*gi[lj + 32] + bi[lj + 32];
        }
    }
    __syncthreads();

    int cg = t >> 4, rg = t & 15;
    int c0 = cg * 8;
    int r0 = rg * 8;

    unsigned long long acc[8][4];
    {
        unsigned long long bp[4];
        #pragma unroll
        for (int cp = 0; cp < 4; cp++)
            asm("mov.b64 %0, {%1, %2};" : "=l"(bp[cp])
                : "f"(bias_sh[c0 + 2*cp]), "f"(bias_sh[c0 + 2*cp + 1]));
        #pragma unroll
        for (int r = 0; r < 8; r++)
            #pragma unroll
            for (int cp = 0; cp < 4; cp++) acc[r][cp] = bp[cp];
    }

    // ---- GEMM mainloop (identical to R12) ----
    #pragma unroll 4
    for (int j = 0; j < 64; j++) {
        const ulonglong2* wp = (const ulonglong2*)&WT[j*132 + c0];
        ulonglong2 wA = wp[0], wB = wp[1];
        #pragma unroll
        for (int r = 0; r < 8; r++) {
            float xv = xs[(r0 + r)*64 + ((j + rg) & 63)];
            unsigned long long x2;
            asm("mov.b64 %0, {%1, %1};" : "=l"(x2) : "f"(xv));
            asm("fma.rn.f32x2 %0, %1, %2, %0;" : "+l"(acc[r][0]) : "l"(x2), "l"(wA.x));
            asm("fma.rn.f32x2 %0, %1, %2, %0;" : "+l"(acc[r][1]) : "l"(x2), "l"(wA.y));
            asm("fma.rn.f32x2 %0, %1, %2, %0;" : "+l"(acc[r][2]) : "l"(x2), "l"(wB.x));
            asm("fma.rn.f32x2 %0, %1, %2, %0;" : "+l"(acc[r][3]) : "l"(x2), "l"(wB.y));
        }
    }

    float af[8][8];
    #pragma unroll
    for (int r = 0; r < 8; r++)
        #pragma unroll
        for (int cp = 0; cp < 4; cp++)
            asm("mov.b64 {%0, %1}, %2;" : "=f"(af[r][2*cp]), "=f"(af[r][2*cp+1]) : "l"(acc[r][cp]));

    __syncthreads();   // xs/WT now dead; safe to overwrite

    // ---- stage results into smem ----
    float* vst = xs;   // [r][(c + 4*rg)&63], r local row, c local v-col
    float* kst = WT;   // [c][n] stride 132

    if (c0 < 64) {
        // k: column vectors, contiguous n per col
        #pragma unroll
        for (int c = 0; c < 8; c++) {
            float* dstc = kst + (c0 + c)*132 + r0;
            *(float4*)(dstc)     = make_float4(af[0][c], af[1][c], af[2][c], af[3][c]);
            *(float4*)(dstc + 4) = make_float4(af[4][c], af[5][c], af[6][c], af[7][c]);
        }
    } else {
        int cv = c0 - 64;
        int rot = 4*rg;
        #pragma unroll
        for (int r = 0; r < 8; r++) {
            float* dstr = vst + (r0 + r)*64;
            int p0 = (cv + rot) & 63;          // mult of 4; c block of 8 doesn't wrap mid-float4
            *(float4*)(dstr + p0)            = make_float4(af[r][0], af[r][1], af[r][2], af[r][3]);
            *(float4*)(dstr + ((p0+4)&63))   = make_float4(af[r][4], af[r][5], af[r][6], af[r][7]);
        }
    }
    __syncthreads();

    // ---- coalesced global stores ----
    // k: 2048 float4s; i = t + 256*chunk; col = i>>5, nq = i&31
    #pragma unroll
    for (int chunk = 0; chunk < 8; chunk++) {
        int i = t + 256*chunk;
        int c = i >> 5, nq = i & 31;
        float4 val = *(const float4*)(kst + c*132 + nq*4);
        *(float4*)(g_k + ((size_t)(b*64 + c))*NN + n0 + nq*4) = val;
    }
    // v: 2048 float4s; i = t + 256*chunk; r = i>>4, pq = i&15
    #pragma unroll
    for (int chunk = 0; chunk < 8; chunk++) {
        int i = t + 256*chunk;
        int r = i >> 4, pq = i & 15;
        int p = pq*4;
        int c = (p - 4*(r >> 3)) & 63;        // invert rotation; no wrap within float4
        float4 val = *(const float4*)(vst + r*64 + p);
        *(float4*)(g_v + (row0 + r)*DD + c) = val;
    }
}

// ============================================================
// Attention v2 (unchanged from R12): grid (32, B), 256 thr.
// ============================================================
__global__ void __launch_bounds__(256) attn_kernel()
{
    int b = blockIdx.y;
    int t = threadIdx.x;
    __shared__ __align__(16) float q_sh[NSL*DD];
    __shared__ __align__(16) float attn_sh[512][8];     // 16 KB
    __shared__ __align__(16) float4 red4[16][16][NSL];  // 28 KB
    __shared__ float S_sh[NSL];

    for (int e = t; e < NSL*DD; e += 256) q_sh[e] = g_q[b*NSL*DD + e];
    if (t < NSL) S_sh[t] = 0.f;
    __syncthreads();

    int n0 = blockIdx.x * 512;

    float S_loc[NSL];
    #pragma unroll
    for (int i = 0; i < NSL; i++) S_loc[i] = 0.f;
    {
        const float* kb = g_k + ((size_t)b*64)*NN + n0 + 2*t;
        float acc[NSL][2];
        #pragma unroll
        for (int i = 0; i < NSL; i++) { acc[i][0] = 0.f; acc[i][1] = 0.f; }

        #pragma unroll 4
        for (int dc = 0; dc < 16; dc++) {
            float2 k0 = *(const float2*)(kb + (size_t)(4*dc+0)*NN);
            float2 k1 = *(const float2*)(kb + (size_t)(4*dc+1)*NN);
            float2 k2 = *(const float2*)(kb + (size_t)(4*dc+2)*NN);
            float2 k3 = *(const float2*)(kb + (size_t)(4*dc+3)*NN);
            #pragma unroll
            for (int i = 0; i < NSL; i++) {
                float4 q4 = *(const float4*)&q_sh[i*64 + 4*dc];
                acc[i][0] = fmaf(q4.x, k0.x, acc[i][0]);
                acc[i][1] = fmaf(q4.x, k0.y, acc[i][1]);
                acc[i][0] = fmaf(q4.y, k1.x, acc[i][0]);
                acc[i][1] = fmaf(q4.y, k1.y, acc[i][1]);
                acc[i][0] = fmaf(q4.z, k2.x, acc[i][0]);
                acc[i][1] = fmaf(q4.z, k2.y, acc[i][1]);
                acc[i][0] = fmaf(q4.w, k3.x, acc[i][0]);
                acc[i][1] = fmaf(q4.w, k3.y, acc[i][1]);
            }
        }
        #pragma unroll
        for (int kk = 0; kk < 2; kk++) {
            float mx = acc[0][kk];
            #pragma unroll
            for (int i = 1; i < NSL; i++) mx = fmaxf(mx, acc[i][kk]);
            float e[8]; float ssum = 0.f;
            #pragma unroll
            for (int i = 0; i < NSL; i++) { e[i] = __expf(acc[i][kk] - mx); ssum += e[i]; }
            float inv = __fdividef(1.f, ssum);
            #pragma unroll
            for (int i = 0; i < NSL; i++) {
                float p = fmaf(e[i], inv, 1e-8f);
                e[i] = p; S_loc[i] += p;
            }
            e[7] = 0.f;
            int jl = 2*t + kk;
            *(float4*)&attn_sh[jl][0] = make_float4(e[0], e[1], e[2], e[3]);
            *(float4*)&attn_sh[jl][4] = make_float4(e[4], e[5], e[6], e[7]);
        }
    }
    __syncthreads();

    int g = t >> 4, dq = t & 15;
    float4 U[NSL];
    #pragma unroll
    for (int i = 0; i < NSL; i++) U[i] = make_float4(0.f, 0.f, 0.f, 0.f);
    {
        const float4* vp = (const float4*)(g_v + ((size_t)b*NN + n0 + g*32)*DD) + dq;
        #pragma unroll 4
        for (int jj = 0; jj < 32; jj++) {
            float4 v4 = vp[(size_t)jj*16];
            int jl = g*32 + jj;
            float4 a0 = *(const float4*)&attn_sh[jl][0];
            float4 a1 = *(const float4*)&attn_sh[jl][4];
            U[0].x = fmaf(a0.x, v4.x, U[0].x); U[0].y = fmaf(a0.x, v4.y, U[0].y);
            U[0].z = fmaf(a0.x, v4.z, U[0].z); U[0].w = fmaf(a0.x, v4.w, U[0].w);
            U[1].x = fmaf(a0.y, v4.x, U[1].x); U[1].y = fmaf(a0.y, v4.y, U[1].y);
            U[1].z = fmaf(a0.y, v4.z, U[1].z); U[1].w = fmaf(a0.y, v4.w, U[1].w);
            U[2].x = fmaf(a0.z, v4.x, U[2].x); U[2].y = fmaf(a0.z, v4.y, U[2].y);
            U[2].z = fmaf(a0.z, v4.z, U[2].z); U[2].w = fmaf(a0.z, v4.w, U[2].w);
            U[3].x = fmaf(a0.w, v4.x, U[3].x); U[3].y = fmaf(a0.w, v4.y, U[3].y);
            U[3].z = fmaf(a0.w, v4.z, U[3].z); U[3].w = fmaf(a0.w, v4.w, U[3].w);
            U[4].x = fmaf(a1.x, v4.x, U[4].x); U[4].y = fmaf(a1.x, v4.y, U[4].y);
            U[4].z = fmaf(a1.x, v4.z, U[4].z); U[4].w = fmaf(a1.x, v4.w, U[4].w);
            U[5].x = fmaf(a1.y, v4.x, U[5].x); U[5].y = fmaf(a1.y, v4.y, U[5].y);
            U[5].z = fmaf(a1.y, v4.z, U[5].z); U[5].w = fmaf(a1.y, v4.w, U[5].w);
            U[6].x = fmaf(a1.z, v4.x, U[6].x); U[6].y = fmaf(a1.z, v4.y, U[6].y);
            U[6].z = fmaf(a1.z, v4.z, U[6].z); U[6].w = fmaf(a1.z, v4.w, U[6].w);
        }
    }
    #pragma unroll
    for (int i = 0; i < NSL; i++) red4[g][dq][i] = U[i];
    __syncthreads();

    for (int e = t; e < NSL*DD; e += 256) {
        int i = e >> 6, d = e & 63;
        int dq2 = d >> 2, c = d & 3;
        const float* base = (const float*)&red4[0][dq2][i] + c;
        float s = 0.f;
        #pragma unroll
        for (int gg = 0; gg < 16; gg++)
            s += base[gg*16*NSL*4];
        atomicAdd(&g_U[(b*NSL + i)*DD + d], s);
    }

    #pragma unroll
    for (int i = 0; i < NSL; i++) {
        float sv = wred(S_loc[i]);
        if ((t & 31) == 0) atomicAdd(&S_sh[i], sv);
    }
    __syncthreads();
    if (t < NSL) atomicAdd(&g_S[b*NSL + t], S_sh[t]);
}

// ============================================================
// Prep (unchanged)
// ============================================================
__global__ void __launch_bounds__(448) prep_kernel(
    const float* __restrict__ noise, const float* __restrict__ mu,
    const float* __restrict__ sigma,
    const float* __restrict__ Wq, const float* __restrict__ bq,
    const float* __restrict__ gsl, const float* __restrict__ bsl)
{
    int b = blockIdx.x, t = threadIdx.x;
    __shared__ float sl[NSL*DD], sn[NSL*DD];
    __shared__ float mstat[NSL][2];
    if (t < NSL*DD) {
        int d = t & 63;
        float v = mu[d] + sigma[d]*noise[b*NSL*DD + t];
        sl[t] = v;
        g_slots[b*NSL*DD + t] = v;
        g_U[b*NSL*DD + t] = 0.f;
    }
    if (t < NSL) g_S[b*NSL + t] = 0.f;
    __syncthreads();
    if (t < NSL) {
        float s = 0.f, ss = 0.f;
        for (int j = 0; j < DD; j++) { float x = sl[t*DD + j]; s += x; ss += x*x; }
        float mean = s*(1.f/64.f), var = ss*(1.f/64.f) - mean*mean;
        mstat[t][0] = mean; mstat[t][1] = rsqrtf(var + 1e-5f);
    }
    __syncthreads();
    if (t < NSL*DD) {
        int i = t >> 6, d = t & 63;
        sn[t] = (sl[t] - mstat[i][0])*mstat[i][1]*gsl[d] + bsl[d];
    }
    __syncthreads();
    if (t < NSL*DD) {
        int i = t >> 6, d = t & 63;
        float q = bq[d];
        for (int j = 0; j < DD; j++) q = fmaf(sn[i*DD + j], Wq[d*DD + j], q);
        g_q[b*NSL*DD + t] = q * 0.125f;
    }
}

// ============================================================
// Finish v3 (unchanged)
// ============================================================
__global__ void __launch_bounds__(512) finish_kernel(
    const float* __restrict__ W_ih, const float* __restrict__ W_hh,
    const float* __restrict__ b_ih, const float* __restrict__ b_hh,
    const float* __restrict__ mW1, const float* __restrict__ mb1,
    const float* __restrict__ mW2, const float* __restrict__ mb2,
    const float* __restrict__ gml, const float* __restrict__ bml,
    const float* __restrict__ Wq,  const float* __restrict__ bq,
    const float* __restrict__ gsl, const float* __restrict__ bsl,
    float* __restrict__ out, int is_last)
{
    int slot = blockIdx.x, b = blockIdx.y;
    int t = threadIdx.x, w = t >> 5, lane = t & 31;
    int sb = b*NSL + slot;

    __shared__ float u[64], p[64];
    __shared__ float xg[192], hg[192];
    __shared__ float snew[64], mn[64], hid[128], sfin[64], sq[64];
    __shared__ float stat[2];

    if (t < 64) {
        float S = g_S[sb];
        u[t] = g_U[sb*DD + t] / S;
        p[t] = g_slots[sb*DD + t];
    }
    __syncthreads();
    if (t < 64) g_U[sb*DD + t] = 0.f;
    if (t == 0) g_S[sb] = 0.f;

    float u_lo = u[lane], u_hi = u[lane+32];
    float p_lo = p[lane], p_hi = p[lane+32];
    #pragma unroll
    for (int it = 0; it < 12; it++) {
        int gd = w + 16*it;
        const float* wi = W_ih + gd*DD;
        const float* wh = W_hh + gd*DD;
        float xa = u_lo*wi[lane] + u_hi*wi[lane+32];
        float ha = p_lo*wh[lane] + p_hi*wh[lane+32];
        xa = wred(xa); ha = wred(ha);
        if (lane == 0) { xg[gd] = xa + b_ih[gd]; hg[gd] = ha + b_hh[gd]; }
    }
    __syncthreads();

    if (t < 64) {
        float r = 1.f/(1.f + expf(-(xg[t]      + hg[t])));
        float z = 1.f/(1.f + expf(-(xg[64+t]   + hg[64+t])));
        float n = tanhf(xg[128+t] + r*hg[128+t]);
        snew[t] = (1.f - z)*n + z*p[t];
    }
    __syncthreads();

    if (w == 0) {
        float a = snew[lane], c = snew[lane+32];
        float s  = wred(a + c);
        float ss = wred(a*a + c*c);
        if (lane == 0) {
            float mean = s*(1.f/64.f), var = ss*(1.f/64.f) - mean*mean;
            stat[0] = mean; stat[1] = rsqrtf(var + 1e-5f);
        }
    }
    __syncthreads();
    if (t < 64) mn[t] = (snew[t] - stat[0])*stat[1]*gml[t] + bml[t];
    __syncthreads();

    float m_lo = mn[lane], m_hi = mn[lane+32];
    #pragma unroll
    for (int it = 0; it < 8; it++) {
        int hh = w + 16*it;
        const float* w1 = mW1 + hh*DD;
        float a = m_lo*w1[lane] + m_hi*w1[lane+32];
        a = wred(a);
        if (lane == 0) hid[hh] = fmaxf(a + mb1[hh], 0.f);
    }
    __syncthreads();

    float h0 = hid[lane], h1 = hid[lane+32], h2 = hid[lane+64], h3 = hid[lane+96];
    #pragma unroll
    for (int it = 0; it < 4; it++) {
        int d = w + 16*it;
        const float* w2 = mW2 + d*HH;
        float a = h0*w2[lane] + h1*w2[lane+32] + h2*w2[lane+64] + h3*w2[lane+96];
        a = wred(a);
        if (lane == 0) {
            float vfin = snew[d] + a + mb2[d];
            sfin[d] = vfin;
            g_slots[sb*DD + d] = vfin;
            if (is_last) out[sb*DD + d] = vfin;
        }
    }
    __syncthreads();

    if (w == 0) {
        float a = sfin[lane], c = sfin[lane+32];
        float s  = wred(a + c);
        float ss = wred(a*a + c*c);
        if (lane == 0) {
            float mean = s*(1.f/64.f), var = ss*(1.f/64.f) - mean*mean;
            stat[0] = mean; stat[1] = rsqrtf(var + 1e-5f);
        }
    }
    __syncthreads();
    if (t < 64) sq[t] = (sfin[t] - stat[0])*stat[1]*gsl[t] + bsl[t];
    __syncthreads();

    float s_lo = sq[lane], s_hi = sq[lane+32];
    #pragma unroll
    for (int it = 0; it < 4; it++) {
        int d = w + 16*it;
        const float* wq = Wq + d*DD;
        float a = s_lo*wq[lane] + s_hi*wq[lane+32];
        a = wred(a);
        if (lane == 0) g_q[sb*DD + d] = (a + bq[d]) * 0.125f;
    }
}

// ============================================================
extern "C" void kernel_launch(void* const* d_in, const int* in_sizes, int n_in,
                              void* d_out, int out_size)
{
    const float* inputs = (const float*)d_in[0];
    const float* noise  = (const float*)d_in[1];
    const float* mu     = (const float*)d_in[2];
    const float* sigma  = (const float*)d_in[3];
    const float* Wq     = (const float*)d_in[4];
    const float* bq     = (const float*)d_in[5];
    const float* Wk     = (const float*)d_in[6];
    const float* bk     = (const float*)d_in[7];
    const float* Wv     = (const float*)d_in[8];
    const float* bv     = (const float*)d_in[9];
    const float* W_ih   = (const float*)d_in[10];
    const float* W_hh   = (const float*)d_in[11];
    const float* b_ih   = (const float*)d_in[12];
    const float* b_hh   = (const float*)d_in[13];
    const float* mW1    = (const float*)d_in[14];
    const float* mb1    = (const float*)d_in[15];
    const float* mW2    = (const float*)d_in[16];
    const float* mb2    = (const float*)d_in[17];
    const float* gin    = (const float*)d_in[18];
    const float* bin    = (const float*)d_in[19];
    const float* gsl    = (const float*)d_in[20];
    const float* bsl    = (const float*)d_in[21];
    const float* gml    = (const float*)d_in[22];
    const float* bml    = (const float*)d_in[23];
    float* out = (float*)d_out;

    const int PROJ_SMEM = 16960 * 4;
    static int attr_set = 0;
    if (!attr_set) {
        cudaFuncSetAttribute(proj_kernel, cudaFuncAttributeMaxDynamicSharedMemorySize, PROJ_SMEM);
        attr_set = 1;
    }

    proj_kernel<<<4096, 256, PROJ_SMEM>>>(inputs, Wk, bk, Wv, bv, gin, bin);   // 0
    prep_kernel<<<BB, 448>>>(noise, mu, sigma, Wq, bq, gsl, bsl);              // 1
    dummy_kernel<<<1, 32>>>();                                                 // 2
    for (int it = 0; it < 3; it++) {
        attn_kernel<<<dim3(32, BB), 256>>>();                                  // 3,5,7 -> -s5 lands on attn
        finish_kernel<<<dim3(NSL, BB), 512>>>(W_ih, W_hh, b_ih, b_hh, mW1, mb1, mW2, mb2,
                                              gml, bml, Wq, bq, gsl, bsl, out, (it == 2) ? 1 : 0);
    }
}

// round 15
// speedup vs baseline: 1.9781x; 1.2274x over previous
#include <cuda_runtime.h>

#define BB  32
#define NN  16384
#define DD  64
#define NSL 7
#define HH  128

// ---- scratch (device globals; no allocations allowed) ----
__device__ float g_k[(size_t)BB*NN*DD];   // stored TRANSPOSED: [b][d][n]
__device__ float g_v[(size_t)BB*NN*DD];   // row-major: [b][n][d]
__device__ float g_slots[BB*NSL*DD];
__device__ float g_q[BB*NSL*DD];
__device__ float g_U[BB*NSL*DD];
__device__ float g_S[BB*NSL];

__device__ __forceinline__ float wred(float v) {
    v += __shfl_xor_sync(0xffffffffu, v, 16);
    v += __shfl_xor_sync(0xffffffffu, v, 8);
    v += __shfl_xor_sync(0xffffffffu, v, 4);
    v += __shfl_xor_sync(0xffffffffu, v, 2);
    v += __shfl_xor_sync(0xffffffffu, v, 1);
    return v;
}

__device__ __forceinline__ float to_tf32(float x) {
    unsigned int u;
    asm("cvt.rna.tf32.f32 %0, %1;" : "=r"(u) : "f"(x));
    return __uint_as_float(u);
}

__global__ void dummy_kernel() {}

// ============================================================
// Projection v7: TF32 tensor-core MMA (m16n8k8), fp32 accumulate.
// Block: 256 thr (8 warps), 128 rows x 128 cols (n<64 -> k, else v).
// Warp: 16 rows x 128 cols = 16 n-tiles x 8 k-steps = 128 HMMA.
// smem stride 68 -> conflict-free fragment loads (banks 4*row+col).
// Results staged in dead smem regions, then coalesced STG.128.
// smem: xs[128*68] + ws[128*68] + bias/gi/bi = 70656 B.
// ============================================================
__global__ void __launch_bounds__(256, 2) proj_kernel(
    const float* __restrict__ inp,
    const float* __restrict__ Wk, const float* __restrict__ bk,
    const float* __restrict__ Wv, const float* __restrict__ bv,
    const float* __restrict__ gin, const float* __restrict__ bin)
{
    extern __shared__ float sm[];
    float* xs      = sm;            // [128][68] tf32 LN(x); later v staging [r][68]
    float* ws      = sm + 8704;     // [128][68] tf32 W, n-major; later k staging [c][132]
    float* bias_sh = sm + 17408;    // [128]
    float* gi      = sm + 17536;    // [64]
    float* bi      = sm + 17600;    // [64]

    int t = threadIdx.x;

    // ---- stage W as tf32: ws[n*68 + k] ----
    for (int e = t; e < 8192; e += 256) {
        int n = e >> 6;
        float w = (n < 64) ? Wk[e] : Wv[e - 4096];
        ws[n*68 + (e & 63)] = to_tf32(w);
    }
    if (t < 64) { gi[t] = gin[t]; bi[t] = bin[t]; bias_sh[t] = bk[t]; bias_sh[64+t] = bv[t]; }

    size_t row0 = (size_t)blockIdx.x * 128;
    int b  = (int)(row0 >> 14);
    int n0 = (int)(row0 & 16383);

    // ---- LN: warp per row, 16 passes; tf32-rounded into xs[r][68] ----
    {
        int lrow = t >> 5, lj = t & 31;
        for (int pass = 0; pass < 16; pass++) {
            int r = pass*8 + lrow;
            const float* xrow = inp + (row0 + r)*DD;
            float a = xrow[lj], c2 = xrow[lj + 32];
            float s  = wred(a + c2);
            float ss = wred(a*a + c2*c2);
            float mean = s * (1.f/64.f);
            float var  = ss * (1.f/64.f) - mean*mean;
            float rstd = rsqrtf(var + 1e-5f);
            xs[r*68 + lj]      = to_tf32((a  - mean)*rstd*gi[lj]      + bi[lj]);
            xs[r*68 + lj + 32] = to_tf32((c2 - mean)*rstd*gi[lj + 32] + bi[lj + 32]);
        }
    }
    __syncthreads();

    int w = t >> 5, lane = t & 31;
    int r0 = w * 16;
    int qrow = lane >> 2, qcol = lane & 3;

    // ---- acc init with bias (C frag cols: 2*qcol, 2*qcol+1) ----
    float acc[16][4];
    #pragma unroll
    for (int nt = 0; nt < 16; nt++) {
        int c = nt*8 + 2*qcol;
        float b0 = bias_sh[c], b1 = bias_sh[c+1];
        acc[nt][0] = b0; acc[nt][1] = b1;
        acc[nt][2] = b0; acc[nt][3] = b1;
    }

    // ---- MMA mainloop: 8 k-steps x 16 n-tiles ----
    #pragma unroll
    for (int ks = 0; ks < 8; ks++) {
        int k0 = ks*8;
        unsigned int a0 = __float_as_uint(xs[(r0+qrow  )*68 + k0 + qcol    ]);
        unsigned int a1 = __float_as_uint(xs[(r0+qrow+8)*68 + k0 + qcol    ]);
        unsigned int a2 = __float_as_uint(xs[(r0+qrow  )*68 + k0 + qcol + 4]);
        unsigned int a3 = __float_as_uint(xs[(r0+qrow+8)*68 + k0 + qcol + 4]);
        #pragma unroll
        for (int nt = 0; nt < 16; nt++) {
            unsigned int b0 = __float_as_uint(ws[(nt*8+qrow)*68 + k0 + qcol    ]);
            unsigned int b1 = __float_as_uint(ws[(nt*8+qrow)*68 + k0 + qcol + 4]);
            asm("mma.sync.aligned.m16n8k8.row.col.f32.tf32.tf32.f32 "
                "{%0,%1,%2,%3}, {%4,%5,%6,%7}, {%8,%9}, {%0,%1,%2,%3};"
                : "+f"(acc[nt][0]), "+f"(acc[nt][1]), "+f"(acc[nt][2]), "+f"(acc[nt][3])
                : "r"(a0), "r"(a1), "r"(a2), "r"(a3), "r"(b0), "r"(b1));
        }
    }
    __syncthreads();   // xs/ws now dead

    // ---- stage results: k (nt 0..7) -> kst[c][132]; v (nt 8..15) -> vst[r][68] ----
    float* kst = ws;
    float* vst = xs;
    #pragma unroll
    for (int nt = 0; nt < 8; nt++) {
        int c = nt*8 + 2*qcol;
        kst[ c   *132 + r0 + qrow    ] = acc[nt][0];
        kst[(c+1)*132 + r0 + qrow    ] = acc[nt][1];
        kst[ c   *132 + r0 + qrow + 8] = acc[nt][2];
        kst[(c+1)*132 + r0 + qrow + 8] = acc[nt][3];
    }
    #pragma unroll
    for (int nt = 8; nt < 16; nt++) {
        int cv = (nt-8)*8 + 2*qcol;
        vst[(r0+qrow  )*68 + cv    ] = acc[nt][0];
        vst[(r0+qrow  )*68 + cv + 1] = acc[nt][1];
        vst[(r0+qrow+8)*68 + cv    ] = acc[nt][2];
        vst[(r0+qrow+8)*68 + cv + 1] = acc[nt][3];
    }
    __syncthreads();

    // ---- coalesced global stores ----
    #pragma unroll
    for (int chunk = 0; chunk < 8; chunk++) {
        int i = t + 256*chunk;
        int c = i >> 5, nq = i & 31;
        float4 val = *(const float4*)(kst + c*132 + nq*4);
        *(float4*)(g_k + ((size_t)(b*64 + c))*NN + n0 + nq*4) = val;
    }
    #pragma unroll
    for (int chunk = 0; chunk < 8; chunk++) {
        int i = t + 256*chunk;
        int r = i >> 4, pq = i & 15;
        float4 val = *(const float4*)(vst + r*68 + pq*4);
        *(float4*)(g_v + (row0 + r)*DD + pq*4) = val;
    }
}

// ============================================================
// Attention v2 (unchanged from R12): grid (32, B), 256 thr.
// ============================================================
__global__ void __launch_bounds__(256) attn_kernel()
{
    int b = blockIdx.y;
    int t = threadIdx.x;
    __shared__ __align__(16) float q_sh[NSL*DD];
    __shared__ __align__(16) float attn_sh[512][8];     // 16 KB
    __shared__ __align__(16) float4 red4[16][16][NSL];  // 28 KB
    __shared__ float S_sh[NSL];

    for (int e = t; e < NSL*DD; e += 256) q_sh[e] = g_q[b*NSL*DD + e];
    if (t < NSL) S_sh[t] = 0.f;
    __syncthreads();

    int n0 = blockIdx.x * 512;

    float S_loc[NSL];
    #pragma unroll
    for (int i = 0; i < NSL; i++) S_loc[i] = 0.f;
    {
        const float* kb = g_k + ((size_t)b*64)*NN + n0 + 2*t;
        float acc[NSL][2];
        #pragma unroll
        for (int i = 0; i < NSL; i++) { acc[i][0] = 0.f; acc[i][1] = 0.f; }

        #pragma unroll 4
        for (int dc = 0; dc < 16; dc++) {
            float2 k0 = *(const float2*)(kb + (size_t)(4*dc+0)*NN);
            float2 k1 = *(const float2*)(kb + (size_t)(4*dc+1)*NN);
            float2 k2 = *(const float2*)(kb + (size_t)(4*dc+2)*NN);
            float2 k3 = *(const float2*)(kb + (size_t)(4*dc+3)*NN);
            #pragma unroll
            for (int i = 0; i < NSL; i++) {
                float4 q4 = *(const float4*)&q_sh[i*64 + 4*dc];
                acc[i][0] = fmaf(q4.x, k0.x, acc[i][0]);
                acc[i][1] = fmaf(q4.x, k0.y, acc[i][1]);
                acc[i][0] = fmaf(q4.y, k1.x, acc[i][0]);
                acc[i][1] = fmaf(q4.y, k1.y, acc[i][1]);
                acc[i][0] = fmaf(q4.z, k2.x, acc[i][0]);
                acc[i][1] = fmaf(q4.z, k2.y, acc[i][1]);
                acc[i][0] = fmaf(q4.w, k3.x, acc[i][0]);
                acc[i][1] = fmaf(q4.w, k3.y, acc[i][1]);
            }
        }
        #pragma unroll
        for (int kk = 0; kk < 2; kk++) {
            float mx = acc[0][kk];
            #pragma unroll
            for (int i = 1; i < NSL; i++) mx = fmaxf(mx, acc[i][kk]);
            float e[8]; float ssum = 0.f;
            #pragma unroll
            for (int i = 0; i < NSL; i++) { e[i] = __expf(acc[i][kk] - mx); ssum += e[i]; }
            float inv = __fdividef(1.f, ssum);
            #pragma unroll
            for (int i = 0; i < NSL; i++) {
                float p = fmaf(e[i], inv, 1e-8f);
                e[i] = p; S_loc[i] += p;
            }
            e[7] = 0.f;
            int jl = 2*t + kk;
            *(float4*)&attn_sh[jl][0] = make_float4(e[0], e[1], e[2], e[3]);
            *(float4*)&attn_sh[jl][4] = make_float4(e[4], e[5], e[6], e[7]);
        }
    }
    __syncthreads();

    int g = t >> 4, dq = t & 15;
    float4 U[NSL];
    #pragma unroll
    for (int i = 0; i < NSL; i++) U[i] = make_float4(0.f, 0.f, 0.f, 0.f);
    {
        const float4* vp = (const float4*)(g_v + ((size_t)b*NN + n0 + g*32)*DD) + dq;
        #pragma unroll 4
        for (int jj = 0; jj < 32; jj++) {
            float4 v4 = vp[(size_t)jj*16];
            int jl = g*32 + jj;
            float4 a0 = *(const float4*)&attn_sh[jl][0];
            float4 a1 = *(const float4*)&attn_sh[jl][4];
            U[0].x = fmaf(a0.x, v4.x, U[0].x); U[0].y = fmaf(a0.x, v4.y, U[0].y);
            U[0].z = fmaf(a0.x, v4.z, U[0].z); U[0].w = fmaf(a0.x, v4.w, U[0].w);
            U[1].x = fmaf(a0.y, v4.x, U[1].x); U[1].y = fmaf(a0.y, v4.y, U[1].y);
            U[1].z = fmaf(a0.y, v4.z, U[1].z); U[1].w = fmaf(a0.y, v4.w, U[1].w);
            U[2].x = fmaf(a0.z, v4.x, U[2].x); U[2].y = fmaf(a0.z, v4.y, U[2].y);
            U[2].z = fmaf(a0.z, v4.z, U[2].z); U[2].w = fmaf(a0.z, v4.w, U[2].w);
            U[3].x = fmaf(a0.w, v4.x, U[3].x); U[3].y = fmaf(a0.w, v4.y, U[3].y);
            U[3].z = fmaf(a0.w, v4.z, U[3].z); U[3].w = fmaf(a0.w, v4.w, U[3].w);
            U[4].x = fmaf(a1.x, v4.x, U[4].x); U[4].y = fmaf(a1.x, v4.y, U[4].y);
            U[4].z = fmaf(a1.x, v4.z, U[4].z); U[4].w = fmaf(a1.x, v4.w, U[4].w);
            U[5].x = fmaf(a1.y, v4.x, U[5].x); U[5].y = fmaf(a1.y, v4.y, U[5].y);
            U[5].z = fmaf(a1.y, v4.z, U[5].z); U[5].w = fmaf(a1.y, v4.w, U[5].w);
            U[6].x = fmaf(a1.z, v4.x, U[6].x); U[6].y = fmaf(a1.z, v4.y, U[6].y);
            U[6].z = fmaf(a1.z, v4.z, U[6].z); U[6].w = fmaf(a1.z, v4.w, U[6].w);
        }
    }
    #pragma unroll
    for (int i = 0; i < NSL; i++) red4[g][dq][i] = U[i];
    __syncthreads();

    for (int e = t; e < NSL*DD; e += 256) {
        int i = e >> 6, d = e & 63;
        int dq2 = d >> 2, c = d & 3;
        const float* base = (const float*)&red4[0][dq2][i] + c;
        float s = 0.f;
        #pragma unroll
        for (int gg = 0; gg < 16; gg++)
            s += base[gg*16*NSL*4];
        atomicAdd(&g_U[(b*NSL + i)*DD + d], s);
    }

    #pragma unroll
    for (int i = 0; i < NSL; i++) {
        float sv = wred(S_loc[i]);
        if ((t & 31) == 0) atomicAdd(&S_sh[i], sv);
    }
    __syncthreads();
    if (t < NSL) atomicAdd(&g_S[b*NSL + t], S_sh[t]);
}

// ============================================================
// Prep (unchanged)
// ============================================================
__global__ void __launch_bounds__(448) prep_kernel(
    const float* __restrict__ noise, const float* __restrict__ mu,
    const float* __restrict__ sigma,
    const float* __restrict__ Wq, const float* __restrict__ bq,
    const float* __restrict__ gsl, const float* __restrict__ bsl)
{
    int b = blockIdx.x, t = threadIdx.x;
    __shared__ float sl[NSL*DD], sn[NSL*DD];
    __shared__ float mstat[NSL][2];
    if (t < NSL*DD) {
        int d = t & 63;
        float v = mu[d] + sigma[d]*noise[b*NSL*DD + t];
        sl[t] = v;
        g_slots[b*NSL*DD + t] = v;
        g_U[b*NSL*DD + t] = 0.f;
    }
    if (t < NSL) g_S[b*NSL + t] = 0.f;
    __syncthreads();
    if (t < NSL) {
        float s = 0.f, ss = 0.f;
        for (int j = 0; j < DD; j++) { float x = sl[t*DD + j]; s += x; ss += x*x; }
        float mean = s*(1.f/64.f), var = ss*(1.f/64.f) - mean*mean;
        mstat[t][0] = mean; mstat[t][1] = rsqrtf(var + 1e-5f);
    }
    __syncthreads();
    if (t < NSL*DD) {
        int i = t >> 6, d = t & 63;
        sn[t] = (sl[t] - mstat[i][0])*mstat[i][1]*gsl[d] + bsl[d];
    }
    __syncthreads();
    if (t < NSL*DD) {
        int i = t >> 6, d = t & 63;
        float q = bq[d];
        for (int j = 0; j < DD; j++) q = fmaf(sn[i*DD + j], Wq[d*DD + j], q);
        g_q[b*NSL*DD + t] = q * 0.125f;
    }
}

// ============================================================
// Finish v3 (unchanged)
// ============================================================
__global__ void __launch_bounds__(512) finish_kernel(
    const float* __restrict__ W_ih, const float* __restrict__ W_hh,
    const float* __restrict__ b_ih, const float* __restrict__ b_hh,
    const float* __restrict__ mW1, const float* __restrict__ mb1,
    const float* __restrict__ mW2, const float* __restrict__ mb2,
    const float* __restrict__ gml, const float* __restrict__ bml,
    const float* __restrict__ Wq,  const float* __restrict__ bq,
    const float* __restrict__ gsl, const float* __restrict__ bsl,
    float* __restrict__ out, int is_last)
{
    int slot = blockIdx.x, b = blockIdx.y;
    int t = threadIdx.x, w = t >> 5, lane = t & 31;
    int sb = b*NSL + slot;

    __shared__ float u[64], p[64];
    __shared__ float xg[192], hg[192];
    __shared__ float snew[64], mn[64], hid[128], sfin[64], sq[64];
    __shared__ float stat[2];

    if (t < 64) {
        float S = g_S[sb];
        u[t] = g_U[sb*DD + t] / S;
        p[t] = g_slots[sb*DD + t];
    }
    __syncthreads();
    if (t < 64) g_U[sb*DD + t] = 0.f;
    if (t == 0) g_S[sb] = 0.f;

    float u_lo = u[lane], u_hi = u[lane+32];
    float p_lo = p[lane], p_hi = p[lane+32];
    #pragma unroll
    for (int it = 0; it < 12; it++) {
        int gd = w + 16*it;
        const float* wi = W_ih + gd*DD;
        const float* wh = W_hh + gd*DD;
        float xa = u_lo*wi[lane] + u_hi*wi[lane+32];
        float ha = p_lo*wh[lane] + p_hi*wh[lane+32];
        xa = wred(xa); ha = wred(ha);
        if (lane == 0) { xg[gd] = xa + b_ih[gd]; hg[gd] = ha + b_hh[gd]; }
    }
    __syncthreads();

    if (t < 64) {
        float r = 1.f/(1.f + expf(-(xg[t]      + hg[t])));
        float z = 1.f/(1.f + expf(-(xg[64+t]   + hg[64+t])));
        float n = tanhf(xg[128+t] + r*hg[128+t]);
        snew[t] = (1.f - z)*n + z*p[t];
    }
    __syncthreads();

    if (w == 0) {
        float a = snew[lane], c = snew[lane+32];
        float s  = wred(a + c);
        float ss = wred(a*a + c*c);
        if (lane == 0) {
            float mean = s*(1.f/64.f), var = ss*(1.f/64.f) - mean*mean;
            stat[0] = mean; stat[1] = rsqrtf(var + 1e-5f);
        }
    }
    __syncthreads();
    if (t < 64) mn[t] = (snew[t] - stat[0])*stat[1]*gml[t] + bml[t];
    __syncthreads();

    float m_lo = mn[lane], m_hi = mn[lane+32];
    #pragma unroll
    for (int it = 0; it < 8; it++) {
        int hh = w + 16*it;
        const float* w1 = mW1 + hh*DD;
        float a = m_lo*w1[lane] + m_hi*w1[lane+32];
        a = wred(a);
        if (lane == 0) hid[hh] = fmaxf(a + mb1[hh], 0.f);
    }
    __syncthreads();

    float h0 = hid[lane], h1 = hid[lane+32], h2 = hid[lane+64], h3 = hid[lane+96];
    #pragma unroll
    for (int it = 0; it < 4; it++) {
        int d = w + 16*it;
        const float* w2 = mW2 + d*HH;
        float a = h0*w2[lane] + h1*w2[lane+32] + h2*w2[lane+64] + h3*w2[lane+96];
        a = wred(a);
        if (lane == 0) {
            float vfin = snew[d] + a + mb2[d];
            sfin[d] = vfin;
            g_slots[sb*DD + d] = vfin;
            if (is_last) out[sb*DD + d] = vfin;
        }
    }
    __syncthreads();

    if (w == 0) {
        float a = sfin[lane], c = sfin[lane+32];
        float s  = wred(a + c);
        float ss = wred(a*a + c*c);
        if (lane == 0) {
            float mean = s*(1.f/64.f), var = ss*(1.f/64.f) - mean*mean;
            stat[0] = mean; stat[1] = rsqrtf(var + 1e-5f);
        }
    }
    __syncthreads();
    if (t < 64) sq[t] = (sfin[t] - stat[0])*stat[1]*gsl[t] + bsl[t];
    __syncthreads();

    float s_lo = sq[lane], s_hi = sq[lane+32];
    #pragma unroll
    for (int it = 0; it < 4; it++) {
        int d = w + 16*it;
        const float* wq = Wq + d*DD;
        float a = s_lo*wq[lane] + s_hi*wq[lane+32];
        a = wred(a);
        if (lane == 0) g_q[sb*DD + d] = (a + bq[d]) * 0.125f;
    }
}

// ============================================================
extern "C" void kernel_launch(void* const* d_in, const int* in_sizes, int n_in,
                              void* d_out, int out_size)
{
    const float* inputs = (const float*)d_in[0];
    const float* noise  = (const float*)d_in[1];
    const float* mu     = (const float*)d_in[2];
    const float* sigma  = (const float*)d_in[3];
    const float* Wq     = (const float*)d_in[4];
    const float* bq     = (const float*)d_in[5];
    const float* Wk     = (const float*)d_in[6];
    const float* bk     = (const float*)d_in[7];
    const float* Wv     = (const float*)d_in[8];
    const float* bv     = (const float*)d_in[9];
    const float* W_ih   = (const float*)d_in[10];
    const float* W_hh   = (const float*)d_in[11];
    const float* b_ih   = (const float*)d_in[12];
    const float* b_hh   = (const float*)d_in[13];
    const float* mW1    = (const float*)d_in[14];
    const float* mb1    = (const float*)d_in[15];
    const float* mW2    = (const float*)d_in[16];
    const float* mb2    = (const float*)d_in[17];
    const float* gin    = (const float*)d_in[18];
    const float* bin    = (const float*)d_in[19];
    const float* gsl    = (const float*)d_in[20];
    const float* bsl    = (const float*)d_in[21];
    const float* gml    = (const float*)d_in[22];
    const float* bml    = (const float*)d_in[23];
    float* out = (float*)d_out;

    const int PROJ_SMEM = 17664 * 4;   // 70656 B
    static int attr_set = 0;
    if (!attr_set) {
        cudaFuncSetAttribute(proj_kernel, cudaFuncAttributeMaxDynamicSharedMemorySize, PROJ_SMEM);
        attr_set = 1;
    }

    proj_kernel<<<4096, 256, PROJ_SMEM>>>(inputs, Wk, bk, Wv, bv, gin, bin);   // 0
    prep_kernel<<<BB, 448>>>(noise, mu, sigma, Wq, bq, gsl, bsl);              // 1
    dummy_kernel<<<1, 32>>>();                                                 // 2
    for (int it = 0; it < 3; it++) {
        attn_kernel<<<dim3(32, BB), 256>>>();                                  // 3,5,7 -> -s5 lands on attn
        finish_kernel<<<dim3(NSL, BB), 512>>>(W_ih, W_hh, b_ih, b_hh, mW1, mb1, mW2, mb2,
                                              gml, bml, Wq, bq, gsl, bsl, out, (it == 2) ? 1 : 0);
    }
}

// round 16
// speedup vs baseline: 2.3683x; 1.1972x over previous
#include <cuda_runtime.h>
#include <cuda_fp16.h>

#define BB  32
#define NN  16384
#define DD  64
#define NSL 7
#define HH  128

// ---- scratch (device globals; no allocations allowed) ----
__device__ __half g_k[(size_t)BB*NN*DD];   // fp16, TRANSPOSED: [b][d][n]
__device__ __half g_v[(size_t)BB*NN*DD];   // fp16, row-major: [b][n][d]
__device__ float g_slots[BB*NSL*DD];
__device__ float g_q[BB*NSL*DD];
__device__ float g_U[BB*NSL*DD];
__device__ float g_S[BB*NSL];

__device__ __forceinline__ float wred(float v) {
    v += __shfl_xor_sync(0xffffffffu, v, 16);
    v += __shfl_xor_sync(0xffffffffu, v, 8);
    v += __shfl_xor_sync(0xffffffffu, v, 4);
    v += __shfl_xor_sync(0xffffffffu, v, 2);
    v += __shfl_xor_sync(0xffffffffu, v, 1);
    return v;
}

__device__ __forceinline__ float to_tf32(float x) {
    unsigned int u;
    asm("cvt.rna.tf32.f32 %0, %1;" : "=r"(u) : "f"(x));
    return __uint_as_float(u);
}

__global__ void dummy_kernel() {}

// ============================================================
// Projection v8: TF32 MMA (R15) + fp16 k/v stores (half traffic).
// ============================================================
__global__ void __launch_bounds__(256, 2) proj_kernel(
    const float* __restrict__ inp,
    const float* __restrict__ Wk, const float* __restrict__ bk,
    const float* __restrict__ Wv, const float* __restrict__ bv,
    const float* __restrict__ gin, const float* __restrict__ bin)
{
    extern __shared__ float sm[];
    float* xs      = sm;            // [128][68] tf32 LN(x); later v staging [r][68]
    float* ws      = sm + 8704;     // [128][68] tf32 W, n-major; later k staging [c][132]
    float* bias_sh = sm + 17408;    // [128]
    float* gi      = sm + 17536;    // [64]
    float* bi      = sm + 17600;    // [64]

    int t = threadIdx.x;

    for (int e = t; e < 8192; e += 256) {
        int n = e >> 6;
        float w = (n < 64) ? Wk[e] : Wv[e - 4096];
        ws[n*68 + (e & 63)] = to_tf32(w);
    }
    if (t < 64) { gi[t] = gin[t]; bi[t] = bin[t]; bias_sh[t] = bk[t]; bias_sh[64+t] = bv[t]; }

    size_t row0 = (size_t)blockIdx.x * 128;
    int b  = (int)(row0 >> 14);
    int n0 = (int)(row0 & 16383);

    // ---- LN ----
    {
        int lrow = t >> 5, lj = t & 31;
        for (int pass = 0; pass < 16; pass++) {
            int r = pass*8 + lrow;
            const float* xrow = inp + (row0 + r)*DD;
            float a = xrow[lj], c2 = xrow[lj + 32];
            float s  = wred(a + c2);
            float ss = wred(a*a + c2*c2);
            float mean = s * (1.f/64.f);
            float var  = ss * (1.f/64.f) - mean*mean;
            float rstd = rsqrtf(var + 1e-5f);
            xs[r*68 + lj]      = to_tf32((a  - mean)*rstd*gi[lj]      + bi[lj]);
            xs[r*68 + lj + 32] = to_tf32((c2 - mean)*rstd*gi[lj + 32] + bi[lj + 32]);
        }
    }
    __syncthreads();

    int w = t >> 5, lane = t & 31;
    int r0 = w * 16;
    int qrow = lane >> 2, qcol = lane & 3;

    float acc[16][4];
    #pragma unroll
    for (int nt = 0; nt < 16; nt++) {
        int c = nt*8 + 2*qcol;
        float b0 = bias_sh[c], b1 = bias_sh[c+1];
        acc[nt][0] = b0; acc[nt][1] = b1;
        acc[nt][2] = b0; acc[nt][3] = b1;
    }

    #pragma unroll
    for (int ks = 0; ks < 8; ks++) {
        int k0 = ks*8;
        unsigned int a0 = __float_as_uint(xs[(r0+qrow  )*68 + k0 + qcol    ]);
        unsigned int a1 = __float_as_uint(xs[(r0+qrow+8)*68 + k0 + qcol    ]);
        unsigned int a2 = __float_as_uint(xs[(r0+qrow  )*68 + k0 + qcol + 4]);
        unsigned int a3 = __float_as_uint(xs[(r0+qrow+8)*68 + k0 + qcol + 4]);
        #pragma unroll
        for (int nt = 0; nt < 16; nt++) {
            unsigned int b0 = __float_as_uint(ws[(nt*8+qrow)*68 + k0 + qcol    ]);
            unsigned int b1 = __float_as_uint(ws[(nt*8+qrow)*68 + k0 + qcol + 4]);
            asm("mma.sync.aligned.m16n8k8.row.col.f32.tf32.tf32.f32 "
                "{%0,%1,%2,%3}, {%4,%5,%6,%7}, {%8,%9}, {%0,%1,%2,%3};"
                : "+f"(acc[nt][0]), "+f"(acc[nt][1]), "+f"(acc[nt][2]), "+f"(acc[nt][3])
                : "r"(a0), "r"(a1), "r"(a2), "r"(a3), "r"(b0), "r"(b1));
        }
    }
    __syncthreads();   // xs/ws now dead

    float* kst = ws;   // [c][132]
    float* vst = xs;   // [r][68]
    #pragma unroll
    for (int nt = 0; nt < 8; nt++) {
        int c = nt*8 + 2*qcol;
        kst[ c   *132 + r0 + qrow    ] = acc[nt][0];
        kst[(c+1)*132 + r0 + qrow    ] = acc[nt][1];
        kst[ c   *132 + r0 + qrow + 8] = acc[nt][2];
        kst[(c+1)*132 + r0 + qrow + 8] = acc[nt][3];
    }
    #pragma unroll
    for (int nt = 8; nt < 16; nt++) {
        int cv = (nt-8)*8 + 2*qcol;
        vst[(r0+qrow  )*68 + cv    ] = acc[nt][0];
        vst[(r0+qrow  )*68 + cv + 1] = acc[nt][1];
        vst[(r0+qrow+8)*68 + cv    ] = acc[nt][2];
        vst[(r0+qrow+8)*68 + cv + 1] = acc[nt][3];
    }
    __syncthreads();

    // ---- coalesced fp16 global stores (8B per lane) ----
    #pragma unroll
    for (int chunk = 0; chunk < 8; chunk++) {
        int i = t + 256*chunk;
        int c = i >> 5, nq = i & 31;
        float4 val = *(const float4*)(kst + c*132 + nq*4);
        __half2 h0 = __floats2half2_rn(val.x, val.y);
        __half2 h1 = __floats2half2_rn(val.z, val.w);
        *(__half2*)(g_k + ((size_t)(b*64 + c))*NN + n0 + nq*4)     = h0;
        *(__half2*)(g_k + ((size_t)(b*64 + c))*NN + n0 + nq*4 + 2) = h1;
    }
    #pragma unroll
    for (int chunk = 0; chunk < 8; chunk++) {
        int i = t + 256*chunk;
        int r = i >> 4, pq = i & 15;
        float4 val = *(const float4*)(vst + r*68 + pq*4);
        __half2 h0 = __floats2half2_rn(val.x, val.y);
        __half2 h1 = __floats2half2_rn(val.z, val.w);
        *(__half2*)(g_v + (row0 + r)*DD + pq*4)     = h0;
        *(__half2*)(g_v + (row0 + r)*DD + pq*4 + 2) = h1;
    }
}

// ============================================================
// Attention v3: fp16 k/v loads, fp32 math. grid (32, B), 256 thr.
// ============================================================
__global__ void __launch_bounds__(256) attn_kernel()
{
    int b = blockIdx.y;
    int t = threadIdx.x;
    __shared__ __align__(16) float q_sh[NSL*DD];
    __shared__ __align__(16) float attn_sh[512][8];     // 16 KB
    __shared__ __align__(16) float4 red4[16][16][NSL];  // 28 KB
    __shared__ float S_sh[NSL];

    for (int e = t; e < NSL*DD; e += 256) q_sh[e] = g_q[b*NSL*DD + e];
    if (t < NSL) S_sh[t] = 0.f;
    __syncthreads();

    int n0 = blockIdx.x * 512;

    float S_loc[NSL];
    #pragma unroll
    for (int i = 0; i < NSL; i++) S_loc[i] = 0.f;
    {
        const __half* kb = g_k + ((size_t)b*64)*NN + n0 + 2*t;
        float acc[NSL][2];
        #pragma unroll
        for (int i = 0; i < NSL; i++) { acc[i][0] = 0.f; acc[i][1] = 0.f; }

        #pragma unroll 4
        for (int dc = 0; dc < 16; dc++) {
            float2 k0 = __half22float2(*(const __half2*)(kb + (size_t)(4*dc+0)*NN));
            float2 k1 = __half22float2(*(const __half2*)(kb + (size_t)(4*dc+1)*NN));
            float2 k2 = __half22float2(*(const __half2*)(kb + (size_t)(4*dc+2)*NN));
            float2 k3 = __half22float2(*(const __half2*)(kb + (size_t)(4*dc+3)*NN));
            #pragma unroll
            for (int i = 0; i < NSL; i++) {
                float4 q4 = *(const float4*)&q_sh[i*64 + 4*dc];
                acc[i][0] = fmaf(q4.x, k0.x, acc[i][0]);
                acc[i][1] = fmaf(q4.x, k0.y, acc[i][1]);
                acc[i][0] = fmaf(q4.y, k1.x, acc[i][0]);
                acc[i][1] = fmaf(q4.y, k1.y, acc[i][1]);
                acc[i][0] = fmaf(q4.z, k2.x, acc[i][0]);
                acc[i][1] = fmaf(q4.z, k2.y, acc[i][1]);
                acc[i][0] = fmaf(q4.w, k3.x, acc[i][0]);
                acc[i][1] = fmaf(q4.w, k3.y, acc[i][1]);
            }
        }
        #pragma unroll
        for (int kk = 0; kk < 2; kk++) {
            float mx = acc[0][kk];
            #pragma unroll
            for (int i = 1; i < NSL; i++) mx = fmaxf(mx, acc[i][kk]);
            float e[8]; float ssum = 0.f;
            #pragma unroll
            for (int i = 0; i < NSL; i++) { e[i] = __expf(acc[i][kk] - mx); ssum += e[i]; }
            float inv = __fdividef(1.f, ssum);
            #pragma unroll
            for (int i = 0; i < NSL; i++) {
                float p = fmaf(e[i], inv, 1e-8f);
                e[i] = p; S_loc[i] += p;
            }
            e[7] = 0.f;
            int jl = 2*t + kk;
            *(float4*)&attn_sh[jl][0] = make_float4(e[0], e[1], e[2], e[3]);
            *(float4*)&attn_sh[jl][4] = make_float4(e[4], e[5], e[6], e[7]);
        }
    }
    __syncthreads();

    int g = t >> 4, dq = t & 15;
    float4 U[NSL];
    #pragma unroll
    for (int i = 0; i < NSL; i++) U[i] = make_float4(0.f, 0.f, 0.f, 0.f);
    {
        const __half* vp = g_v + ((size_t)b*NN + n0 + g*32)*DD + dq*4;
        #pragma unroll 4
        for (int jj = 0; jj < 32; jj++) {
            __half2 raw0 = *(const __half2*)(vp + (size_t)jj*DD);
            __half2 raw1 = *(const __half2*)(vp + (size_t)jj*DD + 2);
            float2 lo = __half22float2(raw0);
            float2 hi = __half22float2(raw1);
            float4 v4 = make_float4(lo.x, lo.y, hi.x, hi.y);
            int jl = g*32 + jj;
            float4 a0 = *(const float4*)&attn_sh[jl][0];
            float4 a1 = *(const float4*)&attn_sh[jl][4];
            U[0].x = fmaf(a0.x, v4.x, U[0].x); U[0].y = fmaf(a0.x, v4.y, U[0].y);
            U[0].z = fmaf(a0.x, v4.z, U[0].z); U[0].w = fmaf(a0.x, v4.w, U[0].w);
            U[1].x = fmaf(a0.y, v4.x, U[1].x); U[1].y = fmaf(a0.y, v4.y, U[1].y);
            U[1].z = fmaf(a0.y, v4.z, U[1].z); U[1].w = fmaf(a0.y, v4.w, U[1].w);
            U[2].x = fmaf(a0.z, v4.x, U[2].x); U[2].y = fmaf(a0.z, v4.y, U[2].y);
            U[2].z = fmaf(a0.z, v4.z, U[2].z); U[2].w = fmaf(a0.z, v4.w, U[2].w);
            U[3].x = fmaf(a0.w, v4.x, U[3].x); U[3].y = fmaf(a0.w, v4.y, U[3].y);
            U[3].z = fmaf(a0.w, v4.z, U[3].z); U[3].w = fmaf(a0.w, v4.w, U[3].w);
            U[4].x = fmaf(a1.x, v4.x, U[4].x); U[4].y = fmaf(a1.x, v4.y, U[4].y);
            U[4].z = fmaf(a1.x, v4.z, U[4].z); U[4].w = fmaf(a1.x, v4.w, U[4].w);
            U[5].x = fmaf(a1.y, v4.x, U[5].x); U[5].y = fmaf(a1.y, v4.y, U[5].y);
            U[5].z = fmaf(a1.y, v4.z, U[5].z); U[5].w = fmaf(a1.y, v4.w, U[5].w);
            U[6].x = fmaf(a1.z, v4.x, U[6].x); U[6].y = fmaf(a1.z, v4.y, U[6].y);
            U[6].z = fmaf(a1.z, v4.z, U[6].z); U[6].w = fmaf(a1.z, v4.w, U[6].w);
        }
    }
    #pragma unroll
    for (int i = 0; i < NSL; i++) red4[g][dq][i] = U[i];
    __syncthreads();

    for (int e = t; e < NSL*DD; e += 256) {
        int i = e >> 6, d = e & 63;
        int dq2 = d >> 2, c = d & 3;
        const float* base = (const float*)&red4[0][dq2][i] + c;
        float s = 0.f;
        #pragma unroll
        for (int gg = 0; gg < 16; gg++)
            s += base[gg*16*NSL*4];
        atomicAdd(&g_U[(b*NSL + i)*DD + d], s);
    }

    #pragma unroll
    for (int i = 0; i < NSL; i++) {
        float sv = wred(S_loc[i]);
        if ((t & 31) == 0) atomicAdd(&S_sh[i], sv);
    }
    __syncthreads();
    if (t < NSL) atomicAdd(&g_S[b*NSL + t], S_sh[t]);
}

// ============================================================
// Prep (unchanged)
// ============================================================
__global__ void __launch_bounds__(448) prep_kernel(
    const float* __restrict__ noise, const float* __restrict__ mu,
    const float* __restrict__ sigma,
    const float* __restrict__ Wq, const float* __restrict__ bq,
    const float* __restrict__ gsl, const float* __restrict__ bsl)
{
    int b = blockIdx.x, t = threadIdx.x;
    __shared__ float sl[NSL*DD], sn[NSL*DD];
    __shared__ float mstat[NSL][2];
    if (t < NSL*DD) {
        int d = t & 63;
        float v = mu[d] + sigma[d]*noise[b*NSL*DD + t];
        sl[t] = v;
        g_slots[b*NSL*DD + t] = v;
        g_U[b*NSL*DD + t] = 0.f;
    }
    if (t < NSL) g_S[b*NSL + t] = 0.f;
    __syncthreads();
    if (t < NSL) {
        float s = 0.f, ss = 0.f;
        for (int j = 0; j < DD; j++) { float x = sl[t*DD + j]; s += x; ss += x*x; }
        float mean = s*(1.f/64.f), var = ss*(1.f/64.f) - mean*mean;
        mstat[t][0] = mean; mstat[t][1] = rsqrtf(var + 1e-5f);
    }
    __syncthreads();
    if (t < NSL*DD) {
        int i = t >> 6, d = t & 63;
        sn[t] = (sl[t] - mstat[i][0])*mstat[i][1]*gsl[d] + bsl[d];
    }
    __syncthreads();
    if (t < NSL*DD) {
        int i = t >> 6, d = t & 63;
        float q = bq[d];
        for (int j = 0; j < DD; j++) q = fmaf(sn[i*DD + j], Wq[d*DD + j], q);
        g_q[b*NSL*DD + t] = q * 0.125f;
    }
}

// ============================================================
// Finish v3 (unchanged)
// ============================================================
__global__ void __launch_bounds__(512) finish_kernel(
    const float* __restrict__ W_ih, const float* __restrict__ W_hh,
    const float* __restrict__ b_ih, const float* __restrict__ b_hh,
    const float* __restrict__ mW1, const float* __restrict__ mb1,
    const float* __restrict__ mW2, const float* __restrict__ mb2,
    const float* __restrict__ gml, const float* __restrict__ bml,
    const float* __restrict__ Wq,  const float* __restrict__ bq,
    const float* __restrict__ gsl, const float* __restrict__ bsl,
    float* __restrict__ out, int is_last)
{
    int slot = blockIdx.x, b = blockIdx.y;
    int t = threadIdx.x, w = t >> 5, lane = t & 31;
    int sb = b*NSL + slot;

    __shared__ float u[64], p[64];
    __shared__ float xg[192], hg[192];
    __shared__ float snew[64], mn[64], hid[128], sfin[64], sq[64];
    __shared__ float stat[2];

    if (t < 64) {
        float S = g_S[sb];
        u[t] = g_U[sb*DD + t] / S;
        p[t] = g_slots[sb*DD + t];
    }
    __syncthreads();
    if (t < 64) g_U[sb*DD + t] = 0.f;
    if (t == 0) g_S[sb] = 0.f;

    float u_lo = u[lane], u_hi = u[lane+32];
    float p_lo = p[lane], p_hi = p[lane+32];
    #pragma unroll
    for (int it = 0; it < 12; it++) {
        int gd = w + 16*it;
        const float* wi = W_ih + gd*DD;
        const float* wh = W_hh + gd*DD;
        float xa = u_lo*wi[lane] + u_hi*wi[lane+32];
        float ha = p_lo*wh[lane] + p_hi*wh[lane+32];
        xa = wred(xa); ha = wred(ha);
        if (lane == 0) { xg[gd] = xa + b_ih[gd]; hg[gd] = ha + b_hh[gd]; }
    }
    __syncthreads();

    if (t < 64) {
        float r = 1.f/(1.f + expf(-(xg[t]      + hg[t])));
        float z = 1.f/(1.f + expf(-(xg[64+t]   + hg[64+t])));
        float n = tanhf(xg[128+t] + r*hg[128+t]);
        snew[t] = (1.f - z)*n + z*p[t];
    }
    __syncthreads();

    if (w == 0) {
        float a = snew[lane], c = snew[lane+32];
        float s  = wred(a + c);
        float ss = wred(a*a + c*c);
        if (lane == 0) {
            float mean = s*(1.f/64.f), var = ss*(1.f/64.f) - mean*mean;
            stat[0] = mean; stat[1] = rsqrtf(var + 1e-5f);
        }
    }
    __syncthreads();
    if (t < 64) mn[t] = (snew[t] - stat[0])*stat[1]*gml[t] + bml[t];
    __syncthreads();

    float m_lo = mn[lane], m_hi = mn[lane+32];
    #pragma unroll
    for (int it = 0; it < 8; it++) {
        int hh = w + 16*it;
        const float* w1 = mW1 + hh*DD;
        float a = m_lo*w1[lane] + m_hi*w1[lane+32];
        a = wred(a);
        if (lane == 0) hid[hh] = fmaxf(a + mb1[hh], 0.f);
    }
    __syncthreads();

    float h0 = hid[lane], h1 = hid[lane+32], h2 = hid[lane+64], h3 = hid[lane+96];
    #pragma unroll
    for (int it = 0; it < 4; it++) {
        int d = w + 16*it;
        const float* w2 = mW2 + d*HH;
        float a = h0*w2[lane] + h1*w2[lane+32] + h2*w2[lane+64] + h3*w2[lane+96];
        a = wred(a);
        if (lane == 0) {
            float vfin = snew[d] + a + mb2[d];
            sfin[d] = vfin;
            g_slots[sb*DD + d] = vfin;
            if (is_last) out[sb*DD + d] = vfin;
        }
    }
    __syncthreads();

    if (w == 0) {
        float a = sfin[lane], c = sfin[lane+32];
        float s  = wred(a + c);
        float ss = wred(a*a + c*c);
        if (lane == 0) {
            float mean = s*(1.f/64.f), var = ss*(1.f/64.f) - mean*mean;
            stat[0] = mean; stat[1] = rsqrtf(var + 1e-5f);
        }
    }
    __syncthreads();
    if (t < 64) sq[t] = (sfin[t] - stat[0])*stat[1]*gsl[t] + bsl[t];
    __syncthreads();

    float s_lo = sq[lane], s_hi = sq[lane+32];
    #pragma unroll
    for (int it = 0; it < 4; it++) {
        int d = w + 16*it;
        const float* wq = Wq + d*DD;
        float a = s_lo*wq[lane] + s_hi*wq[lane+32];
        a = wred(a);
        if (lane == 0) g_q[sb*DD + d] = (a + bq[d]) * 0.125f;
    }
}

// ============================================================
extern "C" void kernel_launch(void* const* d_in, const int* in_sizes, int n_in,
                              void* d_out, int out_size)
{
    const float* inputs = (const float*)d_in[0];
    const float* noise  = (const float*)d_in[1];
    const float* mu     = (const float*)d_in[2];
    const float* sigma  = (const float*)d_in[3];
    const float* Wq     = (const float*)d_in[4];
    const float* bq     = (const float*)d_in[5];
    const float* Wk     = (const float*)d_in[6];
    const float* bk     = (const float*)d_in[7];
    const float* Wv     = (const float*)d_in[8];
    const float* bv     = (const float*)d_in[9];
    const float* W_ih   = (const float*)d_in[10];
    const float* W_hh   = (const float*)d_in[11];
    const float* b_ih   = (const float*)d_in[12];
    const float* b_hh   = (const float*)d_in[13];
    const float* mW1    = (const float*)d_in[14];
    const float* mb1    = (const float*)d_in[15];
    const float* mW2    = (const float*)d_in[16];
    const float* mb2    = (const float*)d_in[17];
    const float* gin    = (const float*)d_in[18];
    const float* bin    = (const float*)d_in[19];
    const float* gsl    = (const float*)d_in[20];
    const float* bsl    = (const float*)d_in[21];
    const float* gml    = (const float*)d_in[22];
    const float* bml    = (const float*)d_in[23];
    float* out = (float*)d_out;

    const int PROJ_SMEM = 17664 * 4;   // 70656 B
    static int attr_set = 0;
    if (!attr_set) {
        cudaFuncSetAttribute(proj_kernel, cudaFuncAttributeMaxDynamicSharedMemorySize, PROJ_SMEM);
        attr_set = 1;
    }

    proj_kernel<<<4096, 256, PROJ_SMEM>>>(inputs, Wk, bk, Wv, bv, gin, bin);   // 0
    prep_kernel<<<BB, 448>>>(noise, mu, sigma, Wq, bq, gsl, bsl);              // 1
    dummy_kernel<<<1, 32>>>();                                                 // 2
    for (int it = 0; it < 3; it++) {
        attn_kernel<<<dim3(32, BB), 256>>>();                                  // 3,5,7 -> -s5 lands on attn
        finish_kernel<<<dim3(NSL, BB), 512>>>(W_ih, W_hh, b_ih, b_hh, mW1, mb1, mW2, mb2,
                                              gml, bml, Wq, bq, gsl, bsl, out, (it == 2) ? 1 : 0);
    }
}